// round 4
// baseline (speedup 1.0000x reference)
#include <cuda_runtime.h>

// RelativePosition: out[b, k(i,j)] = a[b,j] - a[b,i], j > i, row-major
// strict upper triangle. Row i = contiguous output segment:
//   base(i) = i*(n-1) - i*(i-1)/2, len = n-1-i, out[base+t] = a[i+1+t] - a[i]
//
// R4: R3 design (4 shifted smem copies -> aligned LDS.128; warp-per-row,
// paired g <-> n-2-g; 32-bit incremental bases; aligned streaming STG.128)
// plus:
//  * vectorized CONFLICT-FREE smem fill (2 LDG.128 + 4 STS.128 per thread,
//    consecutive per-lane addresses) replacing scalar 4-way-conflicted fill
//  * __launch_bounds__(256, 8) -> regs<=32 -> 8 resident blocks (64 warps)

#define TPB 256
#define PW  2                 // pairs per warp
#define PPB (PW * (TPB / 32)) // pairs per block = 16
#define NMAX 1024

__device__ __forceinline__ void process_row(
    const float (*__restrict__ sm)[NMAX], float* __restrict__ outb,
    int n, int i, int base, int lid)
{
    int len  = n - 1 - i;
    float ai = sm[0][i];
    int src0 = i + 1;

    int head = (-base) & 3;
    if (head > len) head = len;
    if (lid < head) outb[base + lid] = sm[0][src0 + lid] - ai;

    int rem  = len - head;
    int nvec = rem >> 2;
    int x    = src0 + head;
    int sh   = x & 3;
    const float4* __restrict__ sp = (const float4*)(&sm[sh][x - sh]); // 16B aligned
    float4* __restrict__ dp = (float4*)(outb + base + head);          // 16B aligned

    #pragma unroll 4
    for (int v = lid; v < nvec; v += 32) {
        float4 q = sp[v];
        float4 o = make_float4(q.x - ai, q.y - ai, q.z - ai, q.w - ai);
        __stcs(dp + v, o);
    }

    int tm = rem & 3;
    if (lid < tm) {
        int t = head + (nvec << 2) + lid;
        outb[base + t] = sm[0][src0 + t] - ai;
    }
}

__global__ void __launch_bounds__(TPB, 8)
relpos_kernel(const float* __restrict__ in, float* __restrict__ out,
              int n, int G, int chunks, int P)
{
    __shared__ float sm[4][NMAX];

    int b = blockIdx.x / chunks;
    int c = blockIdx.x - b * chunks;
    const int tid = threadIdx.x;
    const int wid = tid >> 5;
    const int lid = tid & 31;

    const float* __restrict__ arow = in + b * n;
    float* __restrict__ outb = out + b * P;        // b*P < 2^31

    // ---- fill 4 shifted copies: sm[s][k] = a[k+s] (k <= n-1-s valid) ----
    // Conflict-free: per thread 2 LDG.128 + 4 STS.128 at consecutive lane addrs.
    {
        const float4* __restrict__ in4 = (const float4*)arow;
        int nv4 = n >> 2;
        for (int t = tid; t < nv4; t += TPB) {
            float4 q0 = in4[t];
            float4 q1 = in4[(t + 1 < nv4) ? (t + 1) : t];  // clamp; tail garbage unread
            float e[8] = {q0.x, q0.y, q0.z, q0.w, q1.x, q1.y, q1.z, q1.w};
            #pragma unroll
            for (int s = 0; s < 4; ++s) {
                float4 w = make_float4(e[s], e[s + 1], e[s + 2], e[s + 3]);
                *(float4*)(&sm[s][t << 2]) = w;
            }
        }
    }
    __syncthreads();

    int gs = c * PPB + wid * PW;   // this warp's first pair index

    // ---- rows i1 = gs .. gs+PW-1 (ascending, incremental base) ----
    {
        int i = gs;
        int base = i * (n - 1) - ((i * (i - 1)) >> 1);
        #pragma unroll
        for (int p = 0; p < PW; ++p) {
            if (i < G) process_row(sm, outb, n, i, base, lid);
            base += n - 1 - i;
            ++i;
        }
    }
    // ---- rows i2 = n-2-gs, descending (incremental base) ----
    {
        int i2 = n - 2 - gs;
        int base2 = i2 * (n - 1) - ((i2 * (i2 - 1)) >> 1);
        #pragma unroll
        for (int p = 0; p < PW; ++p) {
            int g = gs + p;
            if (g < G && i2 > g) process_row(sm, outb, n, i2, base2, lid);
            base2 -= (n - i2);   // base(i2-1) = base(i2) - len(i2-1)
            --i2;
        }
    }
}

extern "C" void kernel_launch(void* const* d_in, const int* in_sizes, int n_in,
                              void* d_out, int out_size)
{
    const float* in = (const float*)d_in[0];
    float* out = (float*)d_out;

    long long total_in = in_sizes[0];                        // B * n
    int n = (int)(2LL * (long long)out_size / total_in + 1); // 1024
    int B = (int)(total_in / n);                             // 128
    int P = n * (n - 1) / 2;                                 // 523776 < 2^31

    int G = n / 2;                                           // pair groups (512)
    int chunks = (G + PPB - 1) / PPB;                        // 32

    relpos_kernel<<<B * chunks, TPB>>>(in, out, n, G, chunks, P);
}

// round 5
// speedup vs baseline: 1.0375x; 1.0375x over previous
#include <cuda_runtime.h>

// RelativePosition: out[b, k(i,j)] = a[b,j] - a[b,i], j > i, row-major
// strict upper triangle. Row i = contiguous output segment:
//   base(i) = i*(n-1) - i*(i-1)/2, len = n-1-i, out[base+t] = a[i+1+t] - a[i]
//
// R5 = R3 structure (4 shifted smem copies -> aligned LDS.128; warp-per-row,
// rows paired g <-> n-2-g; 32-bit incremental bases; aligned streaming
// STG.128; NATURAL occupancy — R4 proved forcing 8 blocks/SM regresses via
// L1tex queue contention) + R4's conflict-free vectorized smem fill.

#define TPB 256
#define PW  2                 // pairs per warp
#define PPB (PW * (TPB / 32)) // pairs per block = 16
#define NMAX 1024

__device__ __forceinline__ void process_row(
    const float (*__restrict__ sm)[NMAX], float* __restrict__ outb,
    int n, int i, int base, int lid)
{
    int len  = n - 1 - i;
    float ai = sm[0][i];
    int src0 = i + 1;

    int head = (-base) & 3;
    if (head > len) head = len;
    if (lid < head) outb[base + lid] = sm[0][src0 + lid] - ai;

    int rem  = len - head;
    int nvec = rem >> 2;
    int x    = src0 + head;
    int sh   = x & 3;
    const float4* __restrict__ sp = (const float4*)(&sm[sh][x - sh]); // 16B aligned
    float4* __restrict__ dp = (float4*)(outb + base + head);          // 16B aligned

    #pragma unroll 4
    for (int v = lid; v < nvec; v += 32) {
        float4 q = sp[v];
        float4 o = make_float4(q.x - ai, q.y - ai, q.z - ai, q.w - ai);
        __stcs(dp + v, o);
    }

    int tm = rem & 3;
    if (lid < tm) {
        int t = head + (nvec << 2) + lid;
        outb[base + t] = sm[0][src0 + t] - ai;
    }
}

__global__ void __launch_bounds__(TPB)
relpos_kernel(const float* __restrict__ in, float* __restrict__ out,
              int n, int G, int chunks, int P)
{
    __shared__ float sm[4][NMAX];

    int b = blockIdx.x / chunks;
    int c = blockIdx.x - b * chunks;
    const int tid = threadIdx.x;
    const int wid = tid >> 5;
    const int lid = tid & 31;

    const float* __restrict__ arow = in + b * n;
    float* __restrict__ outb = out + b * P;        // b*P < 2^31

    // ---- fill 4 shifted copies: sm[s][k] = a[k+s] (k <= n-1-s valid) ----
    // Conflict-free: per thread 2 LDG.128 (2nd is an L1 hit) + 4 STS.128 at
    // consecutive per-lane addresses. Tail garbage in sm[s][n-s..] is unread.
    {
        const float4* __restrict__ in4 = (const float4*)arow;
        int nv4 = n >> 2;                          // 256 == TPB: single pass
        for (int t = tid; t < nv4; t += TPB) {
            float4 q0 = in4[t];
            float4 q1 = in4[(t + 1 < nv4) ? (t + 1) : t];
            float e[8] = {q0.x, q0.y, q0.z, q0.w, q1.x, q1.y, q1.z, q1.w};
            #pragma unroll
            for (int s = 0; s < 4; ++s) {
                float4 w = make_float4(e[s], e[s + 1], e[s + 2], e[s + 3]);
                *(float4*)(&sm[s][t << 2]) = w;
            }
        }
    }
    __syncthreads();

    int gs = c * PPB + wid * PW;   // this warp's first pair index

    // ---- rows i1 = gs .. gs+PW-1 (ascending, incremental base) ----
    {
        int i = gs;
        int base = i * (n - 1) - ((i * (i - 1)) >> 1);
        #pragma unroll
        for (int p = 0; p < PW; ++p) {
            if (i < G) process_row(sm, outb, n, i, base, lid);
            base += n - 1 - i;
            ++i;
        }
    }
    // ---- rows i2 = n-2-gs, descending (incremental base) ----
    {
        int i2 = n - 2 - gs;
        int base2 = i2 * (n - 1) - ((i2 * (i2 - 1)) >> 1);
        #pragma unroll
        for (int p = 0; p < PW; ++p) {
            int g = gs + p;
            if (g < G && i2 > g) process_row(sm, outb, n, i2, base2, lid);
            base2 -= (n - i2);   // base(i2-1) = base(i2) - len(i2-1)
            --i2;
        }
    }
}

extern "C" void kernel_launch(void* const* d_in, const int* in_sizes, int n_in,
                              void* d_out, int out_size)
{
    const float* in = (const float*)d_in[0];
    float* out = (float*)d_out;

    long long total_in = in_sizes[0];                        // B * n
    int n = (int)(2LL * (long long)out_size / total_in + 1); // 1024
    int B = (int)(total_in / n);                             // 128
    int P = n * (n - 1) / 2;                                 // 523776 < 2^31

    int G = n / 2;                                           // pair groups (512)
    int chunks = (G + PPB - 1) / PPB;                        // 32

    relpos_kernel<<<B * chunks, TPB>>>(in, out, n, G, chunks, P);
}